// round 7
// baseline (speedup 1.0000x reference)
#include <cuda_runtime.h>
#include <cstdint>

// -------------------------------------------------------------------------
// out = Conv2(ReLU(Conv1( sum_t Ht[t,:,:] * upsample4(yt[b,t]) )))
//   yt:(32,32,64,64) Ht:(32,256,256) W1:(32,1,3,3) b1:(32) W2:(1,32,3,3) b2:(1)
//   out:(32,1,256,256) f32
// -------------------------------------------------------------------------

#define B_ 32
#define T_ 32
#define R_ 256

typedef unsigned long long u64;

__device__ float g_x[B_ * R_ * R_];   // stage-1 scratch (8.4 MB static)

// ---- packed f32x2 helpers (sm_103a; ptxas never emits FFMA2 from C++) ----
__device__ __forceinline__ u64 pk2(float lo, float hi) {
    u64 r; asm("mov.b64 %0, {%1,%2};" : "=l"(r) : "f"(lo), "f"(hi)); return r;
}
__device__ __forceinline__ float2 upk2(u64 a) {
    float2 v; asm("mov.b64 {%0,%1}, %2;" : "=f"(v.x), "=f"(v.y) : "l"(a)); return v;
}
__device__ __forceinline__ u64 ffma2(u64 a, u64 b, u64 c) {
    u64 d; asm("fma.rn.f32x2 %0, %1, %2, %3;" : "=l"(d) : "l"(a), "l"(b), "l"(c)); return d;
}
__device__ __forceinline__ u64 fadd2(u64 a, u64 b) {
    u64 d; asm("add.rn.f32x2 %0, %1, %2;" : "=l"(d) : "l"(a), "l"(b)); return d;
}

// ---------------- Stage 1 ----------------
__global__ void __launch_bounds__(256) stage1_kernel(
    const float* __restrict__ yt, const float* __restrict__ Ht)
{
    int idx = blockIdx.x * 256 + threadIdx.x;
    int p = idx >> 8;
    int q = idx & 255;
    int yoff = ((p >> 2) << 6) + (q >> 2);

    float ht[T_];
#pragma unroll
    for (int t = 0; t < T_; t++)
        ht[t] = Ht[(t << 16) + idx];

    int bbase = blockIdx.y << 4;          // 16 batches per block
#pragma unroll 2
    for (int bo = 0; bo < 16; bo++) {
        int b = bbase + bo;
        const float* ytb = yt + ((long)b << 17) + yoff;
        float acc = 0.f;
#pragma unroll
        for (int t = 0; t < T_; t++)
            acc = fmaf(ht[t], ytb[t << 12], acc);
        g_x[((long)b << 16) + idx] = acc;
    }
}

// ---------------- Stage 2: fused conv1+relu+conv2, f32x2 packed ----------------
#define SXW   44                      // x tile row stride (de-conflicts 12-row bands)
#define SXH   38                      // 36 used + 2 pad rows (marching reads r+2 up to 37)
#define SX_ELEMS (SXH * SXW)          // 1672 floats = 6688 B
#define SHW   36
#define SH_ELEMS (8 * 34 * SHW)       // 39168 B
// sw2p: 288 u64 = 2304 B ; total static smem = 48160 B < 48 KB ✓

struct Row6 { u64 p01, p23, p45, p12, p34; };

// p must be 16-B aligned; loads 6 floats v0..v5 and builds overlap pairs
__device__ __forceinline__ Row6 load_row6(const float* p) {
    Row6 R;
    ulonglong2 q = *(const ulonglong2*)p;     // (v0,v1),(v2,v3)
    u64 t = *(const u64*)(p + 4);             // (v4,v5)
    R.p01 = q.x; R.p23 = q.y; R.p45 = t;
    float2 a = upk2(q.x), b = upk2(q.y), c = upk2(t);
    R.p12 = pk2(a.y, b.x);
    R.p34 = pk2(b.y, c.x);
    return R;
}

__global__ void __launch_bounds__(256) fused_conv_kernel(
    const float* __restrict__ W1, const float* __restrict__ b1,
    const float* __restrict__ W2, const float* __restrict__ b2,
    float* __restrict__ out)
{
    __shared__ __align__(16) float sh[SH_ELEMS];
    __shared__ __align__(16) float sx[SX_ELEMS];
    __shared__ u64 sw2p[32 * 9];

    int tid = threadIdx.x;
    int b   = blockIdx.y;
    int P0  = (blockIdx.x >> 3) << 5;
    int Q0  = (blockIdx.x & 7)  << 5;
    const float* xb = g_x + ((long)b << 16);

    // ---- load x tile (rows P0-2..P0+33 -> sx rows 0..35; rows 36,37 + cols>=36 zero) ----
    for (int i = tid; i < SX_ELEMS; i += 256) {
        int r  = i / SXW;
        int cc = i - r * SXW;
        int gp = P0 - 2 + r;
        int gq = Q0 - 2 + cc;
        float v = 0.f;
        if (cc < 36 && (unsigned)gp < 256u && (unsigned)gq < 256u)
            v = xb[(gp << 8) + gq];
        sx[i] = v;
    }
    // paired conv2 weights (w,w)
    for (int i = tid; i < 32 * 9; i += 256) {
        float f = W2[i];
        sw2p[i] = pk2(f, f);
    }
    __syncthreads();

    // ---- conv1 thread mapping: warp = channel slot c8, lane -> (strip, band) ----
    int c8 = tid >> 5;                 // 0..7
    int u  = tid & 31;
    int uu = (u < 27) ? u : (u - 27);  // lanes 27..31 duplicate (benign same-value stores)
    int s  = uu % 9;                   // col strip 0..8
    int rb = uu / 9;                   // row band 0..2
    int col = s << 2;                  // sh col base 0..32
    int r0  = rb * 12;                 // output rows r0..r0+11 (rows>=34 masked)
    // col masks (h1 out-of-image -> 0), constants per thread
    float cm0 = ((unsigned)(Q0 - 1 + col + 0) < 256u) ? 1.f : 0.f;
    float cm1 = ((unsigned)(Q0 - 1 + col + 1) < 256u) ? 1.f : 0.f;
    float cm2 = ((unsigned)(Q0 - 1 + col + 2) < 256u) ? 1.f : 0.f;
    float cm3 = ((unsigned)(Q0 - 1 + col + 3) < 256u) ? 1.f : 0.f;
    float* shc = sh + c8 * (34 * SHW);
    const float* xp = sx + r0 * SXW + col;

    // ---- conv2 thread mapping: 128 strips (2x4 outputs) x 2 channel-halves ----
    int st   = tid & 127;
    int half = tid >> 7;
    int oy = (st >> 3) << 1;           // 0,2,..,30
    int ox = (st & 7) << 2;            // 0,4,..,28
    float bb = *b2;
    u64 A01, A23, B01, B23;            // packed accumulators, persist across groups
    A01 = A23 = B01 = B23 = (half == 0) ? pk2(bb, bb) : 0ull;

    for (int g = 0; g < 4; g++) {
        // ================= conv1 + relu (marching rows, packed FMA) =================
        {
            int c = (g << 3) + c8;
            const float* wsrc = W1 + c * 9;
            u64 wp[9];
#pragma unroll
            for (int k = 0; k < 9; k++) { float f = __ldg(wsrc + k); wp[k] = pk2(f, f); }
            float bi = __ldg(b1 + c);
            u64 bias2 = pk2(bi, bi);

            Row6 rw[3];
            rw[0] = load_row6(xp);
            rw[1] = load_row6(xp + SXW);
#pragma unroll
            for (int i = 0; i < 12; i++) {
                rw[(i + 2) % 3] = load_row6(xp + (i + 2) * SXW);
                const Row6& A  = rw[i % 3];
                const Row6& Bv = rw[(i + 1) % 3];
                const Row6& C  = rw[(i + 2) % 3];
                u64 a01 = bias2, a23 = bias2;
                a01 = ffma2(wp[0], A.p01, a01);
                a23 = ffma2(wp[0], A.p23, a23);
                a01 = ffma2(wp[1], A.p12, a01);
                a23 = ffma2(wp[1], A.p34, a23);
                a01 = ffma2(wp[2], A.p23, a01);
                a23 = ffma2(wp[2], A.p45, a23);
                a01 = ffma2(wp[3], Bv.p01, a01);
                a23 = ffma2(wp[3], Bv.p23, a23);
                a01 = ffma2(wp[4], Bv.p12, a01);
                a23 = ffma2(wp[4], Bv.p34, a23);
                a01 = ffma2(wp[5], Bv.p23, a01);
                a23 = ffma2(wp[5], Bv.p45, a23);
                a01 = ffma2(wp[6], C.p01, a01);
                a23 = ffma2(wp[6], C.p23, a23);
                a01 = ffma2(wp[7], C.p12, a01);
                a23 = ffma2(wp[7], C.p34, a23);
                a01 = ffma2(wp[8], C.p23, a01);
                a23 = ffma2(wp[8], C.p45, a23);

                int row = r0 + i;
                float mr = ((unsigned)(P0 - 1 + row) < 256u) ? 1.f : 0.f;
                float2 x01 = upk2(a01), x23 = upk2(a23);
                float o0 = fmaxf(x01.x, 0.f) * (mr * cm0);
                float o1 = fmaxf(x01.y, 0.f) * (mr * cm1);
                float o2 = fmaxf(x23.x, 0.f) * (mr * cm2);
                float o3 = fmaxf(x23.y, 0.f) * (mr * cm3);
                if (row < 34)
                    *(float4*)(shc + row * SHW + col) = make_float4(o0, o1, o2, o3);
            }
        }
        __syncthreads();

        // ================= conv2 partial accumulation (4 channels per half) =========
        {
#pragma unroll
            for (int cc4 = 0; cc4 < 4; cc4++) {
                int c8v = (half << 2) + cc4;            // 0..7 within group
                int c   = (g << 3) + c8v;               // global channel
                const u64* wz = sw2p + c * 9;
                u64 w9[9];
#pragma unroll
                for (int k = 0; k < 9; k++) w9[k] = wz[k];
                const float* hp = sh + c8v * (34 * SHW) + oy * SHW + ox;

#pragma unroll
                for (int j = 0; j < 4; j++) {
                    Row6 R = load_row6(hp + j * SHW);
                    if (j < 3) {                         // out row 0, dy = j
                        A01 = ffma2(w9[3 * j + 0], R.p01, A01);
                        A23 = ffma2(w9[3 * j + 0], R.p23, A23);
                        A01 = ffma2(w9[3 * j + 1], R.p12, A01);
                        A23 = ffma2(w9[3 * j + 1], R.p34, A23);
                        A01 = ffma2(w9[3 * j + 2], R.p23, A01);
                        A23 = ffma2(w9[3 * j + 2], R.p45, A23);
                    }
                    if (j >= 1) {                        // out row 1, dy = j-1
                        B01 = ffma2(w9[3 * (j - 1) + 0], R.p01, B01);
                        B23 = ffma2(w9[3 * (j - 1) + 0], R.p23, B23);
                        B01 = ffma2(w9[3 * (j - 1) + 1], R.p12, B01);
                        B23 = ffma2(w9[3 * (j - 1) + 1], R.p34, B23);
                        B01 = ffma2(w9[3 * (j - 1) + 2], R.p23, B01);
                        B23 = ffma2(w9[3 * (j - 1) + 2], R.p45, B23);
                    }
                }
            }
        }
        __syncthreads();    // before next group overwrites sh (also orders last group)
    }

    // ---- combine channel-halves via smem (reuse sx region; conv1 done with it) ----
    u64* red = (u64*)sx;
    if (half == 1) {
        red[st * 4 + 0] = A01;
        red[st * 4 + 1] = A23;
        red[st * 4 + 2] = B01;
        red[st * 4 + 3] = B23;
    }
    __syncthreads();
    if (half == 0) {
        A01 = fadd2(A01, red[st * 4 + 0]);
        A23 = fadd2(A23, red[st * 4 + 1]);
        B01 = fadd2(B01, red[st * 4 + 2]);
        B23 = fadd2(B23, red[st * 4 + 3]);
        float2 a = upk2(A01), b2v = upk2(A23), c = upk2(B01), d = upk2(B23);
        float* ob = out + ((long)b << 16) + ((P0 + oy) << 8) + Q0 + ox;
        *(float4*)ob         = make_float4(a.x, a.y, b2v.x, b2v.y);
        *(float4*)(ob + 256) = make_float4(c.x, c.y, d.x, d.y);
    }
}

// -------------------------------------------------------------------------
extern "C" void kernel_launch(void* const* d_in, const int* in_sizes, int n_in,
                              void* d_out, int out_size)
{
    const float* yt = (const float*)d_in[0];
    const float* Ht = (const float*)d_in[1];
    const float* W1 = (const float*)d_in[2];
    const float* b1 = (const float*)d_in[3];
    const float* W2 = (const float*)d_in[4];
    const float* b2 = (const float*)d_in[5];
    float* out = (float*)d_out;

    stage1_kernel<<<dim3(256, 2), 256>>>(yt, Ht);
    fused_conv_kernel<<<dim3(64, 32), 256>>>(W1, b1, W2, b2, out);
}

// round 8
// speedup vs baseline: 1.7379x; 1.7379x over previous
#include <cuda_runtime.h>

// -------------------------------------------------------------------------
// out = Conv2(ReLU(Conv1( sum_t Ht[t,:,:] * upsample4(yt[b,t]) )))
//   yt:(32,32,64,64) Ht:(32,256,256) W1:(32,1,3,3) b1:(32) W2:(1,32,3,3) b2:(1)
//   out:(32,1,256,256) f32
// -------------------------------------------------------------------------

#define B_ 32
#define T_ 32
#define R_ 256

__device__ float g_x[B_ * R_ * R_];   // stage-1 scratch (8.4 MB static)

// ---------------- Stage 1 ----------------
__global__ void __launch_bounds__(256) stage1_kernel(
    const float* __restrict__ yt, const float* __restrict__ Ht)
{
    int idx = blockIdx.x * 256 + threadIdx.x;
    int p = idx >> 8;
    int q = idx & 255;
    int yoff = ((p >> 2) << 6) + (q >> 2);

    float ht[T_];
#pragma unroll
    for (int t = 0; t < T_; t++)
        ht[t] = Ht[(t << 16) + idx];

    int bbase = blockIdx.y << 3;          // 8 batches per block
#pragma unroll 2
    for (int bo = 0; bo < 8; bo++) {
        int b = bbase + bo;
        const float* ytb = yt + ((long)b << 17) + yoff;
        float acc = 0.f;
#pragma unroll
        for (int t = 0; t < T_; t++)
            acc = fmaf(ht[t], ytb[t << 12], acc);
        g_x[((long)b << 16) + idx] = acc;
    }
}

// ---------------- Stage 2: fused conv1+relu+conv2 ----------------
//   sx : [36][40]     x tile rows P0-2..P0+33 (36 cols), zero halo
//   sh : [8][34][36]  current group's h1 (zeroed outside image)
//   sw1/sb1/sw2 : weights staged for broadcast LDS
#define SHW 36
#define SH_ELEMS (8 * 34 * SHW)     // 39168 B
#define SX_ELEMS (36 * 40)          //  5760 B

__global__ void __launch_bounds__(256) fused_conv_kernel(
    const float* __restrict__ W1, const float* __restrict__ b1,
    const float* __restrict__ W2, const float* __restrict__ b2,
    float* __restrict__ out)
{
    __shared__ __align__(16) float sh[SH_ELEMS];
    __shared__ __align__(16) float sx[SX_ELEMS];
    __shared__ float sw1[288];
    __shared__ float sb1[32];
    __shared__ float sw2[288];

    int tid = threadIdx.x;
    int b   = blockIdx.y;
    int P0  = (blockIdx.x >> 3) << 5;
    int Q0  = (blockIdx.x & 7)  << 5;
    const float* xb = g_x + ((long)b << 16);

    // ---- stage weights + x tile ----
    for (int i = tid; i < 288; i += 256) { sw1[i] = W1[i]; sw2[i] = W2[i]; }
    if (tid < 32) sb1[tid] = b1[tid];
    for (int i = tid; i < SX_ELEMS; i += 256) {
        int r  = i / 40;
        int cc = i - r * 40;
        int gp = P0 - 2 + r;
        int gq = Q0 - 2 + cc;
        float v = 0.f;
        if (cc < 36 && (unsigned)gp < 256u && (unsigned)gq < 256u)
            v = xb[(gp << 8) + gq];
        sx[i] = v;
    }
    __syncthreads();

    // conv1 mapping: 4 channel-pair slots x 64 spatial threads
    int pr = tid >> 6;            // 0..3 -> channels 2*pr, 2*pr+1 of group
    int u0 = tid & 63;

    // conv2 mapping: 128 strips (2 rows x 4 cols) x 2 channel-halves
    int st   = tid & 127;
    int half = tid >> 7;
    int oy = (st >> 3) << 1;      // 0,2,..,30
    int ox = (st & 7) << 2;       // 0,4,..,28
    float bb = *b2;
    float aA0, aA1, aA2, aA3, aB0, aB1, aB2, aB3;   // persistent accumulators
    aA0 = aA1 = aA2 = aA3 = aB0 = aB1 = aB2 = aB3 = (half == 0) ? bb : 0.f;
    // b2 bias folded into half 0 only (row0 & row1 strips)

    for (int g = 0; g < 4; g++) {
        // ============ conv1 + relu: 2 channels per thread, x reused ============
        {
            int c0 = (g << 3) + (pr << 1);
            float w0[9], w1[9];
#pragma unroll
            for (int k = 0; k < 9; k++) { w0[k] = sw1[c0 * 9 + k]; w1[k] = sw1[c0 * 9 + 9 + k]; }
            float bi0 = sb1[c0], bi1 = sb1[c0 + 1];
            float* sh0 = sh + (pr << 1) * (34 * SHW);
            float* sh1 = sh0 + 34 * SHW;

#pragma unroll
            for (int k = 0; k < 5; k++) {
                int unit = u0 + (k << 6);
                if (unit < 306) {
                    int r   = unit / 9;
                    int col = (unit - r * 9) << 2;       // 0..32
                    const float* x0 = sx + r * 40 + col;
                    // load 3 rows x 6 floats once
                    float v[3][6];
#pragma unroll
                    for (int dy = 0; dy < 3; dy++) {
                        float4 q4 = *(const float4*)(x0 + dy * 40);
                        float2 q2 = *(const float2*)(x0 + dy * 40 + 4);
                        v[dy][0] = q4.x; v[dy][1] = q4.y; v[dy][2] = q4.z;
                        v[dy][3] = q4.w; v[dy][4] = q2.x; v[dy][5] = q2.y;
                    }
                    float a0 = bi0, a1 = bi0, a2 = bi0, a3 = bi0;
                    float c0a = bi1, c1a = bi1, c2a = bi1, c3a = bi1;
#pragma unroll
                    for (int dy = 0; dy < 3; dy++) {
#pragma unroll
                        for (int dx = 0; dx < 3; dx++) {
                            float wa = w0[dy * 3 + dx], wb = w1[dy * 3 + dx];
                            a0  = fmaf(wa, v[dy][dx + 0], a0);
                            a1  = fmaf(wa, v[dy][dx + 1], a1);
                            a2  = fmaf(wa, v[dy][dx + 2], a2);
                            a3  = fmaf(wa, v[dy][dx + 3], a3);
                            c0a = fmaf(wb, v[dy][dx + 0], c0a);
                            c1a = fmaf(wb, v[dy][dx + 1], c1a);
                            c2a = fmaf(wb, v[dy][dx + 2], c2a);
                            c3a = fmaf(wb, v[dy][dx + 3], c3a);
                        }
                    }
                    // relu + zero h1 outside image (conv2 SAME padding)
                    float mr  = ((unsigned)(P0 - 1 + r) < 256u) ? 1.f : 0.f;
                    int   gq  = Q0 - 1 + col;
                    float m0 = mr * (((unsigned)(gq + 0) < 256u) ? 1.f : 0.f);
                    float m1 = mr * (((unsigned)(gq + 1) < 256u) ? 1.f : 0.f);
                    float m2 = mr * (((unsigned)(gq + 2) < 256u) ? 1.f : 0.f);
                    float m3 = mr * (((unsigned)(gq + 3) < 256u) ? 1.f : 0.f);
                    *(float4*)(sh0 + r * SHW + col) = make_float4(
                        fmaxf(a0, 0.f) * m0, fmaxf(a1, 0.f) * m1,
                        fmaxf(a2, 0.f) * m2, fmaxf(a3, 0.f) * m3);
                    *(float4*)(sh1 + r * SHW + col) = make_float4(
                        fmaxf(c0a, 0.f) * m0, fmaxf(c1a, 0.f) * m1,
                        fmaxf(c2a, 0.f) * m2, fmaxf(c3a, 0.f) * m3);
                }
            }
        }
        __syncthreads();

        // ============ conv2: 2x4 outputs, 4 channels per half ============
        {
#pragma unroll
            for (int cc = 0; cc < 4; cc++) {
                int c8v = (half << 2) + cc;
                int c   = (g << 3) + c8v;
                float w[9];
#pragma unroll
                for (int k = 0; k < 9; k++) w[k] = sw2[c * 9 + k];
                const float* hp = sh + c8v * (34 * SHW) + oy * SHW + ox;

#pragma unroll
                for (int j = 0; j < 4; j++) {
                    float4 q4 = *(const float4*)(hp + j * SHW);
                    float2 q2 = *(const float2*)(hp + j * SHW + 4);
                    float v0 = q4.x, v1 = q4.y, v2 = q4.z,
                          v3 = q4.w, v4 = q2.x, v5 = q2.y;
                    if (j < 3) {                          // out row 0, dy=j
                        float w0 = w[3 * j], w1 = w[3 * j + 1], w2 = w[3 * j + 2];
                        aA0 = fmaf(w0, v0, aA0); aA0 = fmaf(w1, v1, aA0); aA0 = fmaf(w2, v2, aA0);
                        aA1 = fmaf(w0, v1, aA1); aA1 = fmaf(w1, v2, aA1); aA1 = fmaf(w2, v3, aA1);
                        aA2 = fmaf(w0, v2, aA2); aA2 = fmaf(w1, v3, aA2); aA2 = fmaf(w2, v4, aA2);
                        aA3 = fmaf(w0, v3, aA3); aA3 = fmaf(w1, v4, aA3); aA3 = fmaf(w2, v5, aA3);
                    }
                    if (j >= 1) {                         // out row 1, dy=j-1
                        float w0 = w[3 * (j - 1)], w1 = w[3 * (j - 1) + 1], w2 = w[3 * (j - 1) + 2];
                        aB0 = fmaf(w0, v0, aB0); aB0 = fmaf(w1, v1, aB0); aB0 = fmaf(w2, v2, aB0);
                        aB1 = fmaf(w0, v1, aB1); aB1 = fmaf(w1, v2, aB1); aB1 = fmaf(w2, v3, aB1);
                        aB2 = fmaf(w0, v2, aB2); aB2 = fmaf(w1, v3, aB2); aB2 = fmaf(w2, v4, aB2);
                        aB3 = fmaf(w0, v3, aB3); aB3 = fmaf(w1, v4, aB3); aB3 = fmaf(w2, v5, aB3);
                    }
                }
            }
        }
        __syncthreads();   // before next group's conv1 overwrites sh / reads sx
    }

    // ---- combine channel-halves via smem (sx no longer needed) ----
    float* red = sx;
    if (half == 1) {
        float* rp = red + st * 8;
        rp[0] = aA0; rp[1] = aA1; rp[2] = aA2; rp[3] = aA3;
        rp[4] = aB0; rp[5] = aB1; rp[6] = aB2; rp[7] = aB3;
    }
    __syncthreads();
    if (half == 0) {
        const float* rp = red + st * 8;
        aA0 += rp[0]; aA1 += rp[1]; aA2 += rp[2]; aA3 += rp[3];
        aB0 += rp[4]; aB1 += rp[5]; aB2 += rp[6]; aB3 += rp[7];
        float* ob = out + ((long)b << 16) + ((P0 + oy) << 8) + Q0 + ox;
        *(float4*)ob         = make_float4(aA0, aA1, aA2, aA3);
        *(float4*)(ob + 256) = make_float4(aB0, aB1, aB2, aB3);
    }
}

// -------------------------------------------------------------------------
extern "C" void kernel_launch(void* const* d_in, const int* in_sizes, int n_in,
                              void* d_out, int out_size)
{
    const float* yt = (const float*)d_in[0];
    const float* Ht = (const float*)d_in[1];
    const float* W1 = (const float*)d_in[2];
    const float* b1 = (const float*)d_in[3];
    const float* W2 = (const float*)d_in[4];
    const float* b2 = (const float*)d_in[5];
    float* out = (float*)d_out;

    stage1_kernel<<<dim3(256, 4), 256>>>(yt, Ht);
    fused_conv_kernel<<<dim3(64, 32), 256>>>(W1, b1, W2, b2, out);
}

// round 9
// speedup vs baseline: 1.9039x; 1.0955x over previous
#include <cuda_runtime.h>

// -------------------------------------------------------------------------
// out = Conv2(ReLU(Conv1( sum_t Ht[t,:,:] * upsample4(yt[b,t]) )))
//   yt:(32,32,64,64) Ht:(32,256,256) W1:(32,1,3,3) b1:(32) W2:(1,32,3,3) b2:(1)
//   out:(32,1,256,256) f32
// -------------------------------------------------------------------------

#define B_ 32
#define T_ 32
#define R_ 256

typedef unsigned long long u64;

__device__ float g_x[B_ * R_ * R_];   // stage-1 scratch (8.4 MB static)

// ---- packed f32x2 helpers ----
__device__ __forceinline__ u64 pk2(float lo, float hi) {
    u64 r; asm("mov.b64 %0, {%1,%2};" : "=l"(r) : "f"(lo), "f"(hi)); return r;
}
__device__ __forceinline__ float2 upk2(u64 a) {
    float2 v; asm("mov.b64 {%0,%1}, %2;" : "=f"(v.x), "=f"(v.y) : "l"(a)); return v;
}
__device__ __forceinline__ u64 ffma2(u64 a, u64 b, u64 c) {
    u64 d; asm("fma.rn.f32x2 %0, %1, %2, %3;" : "=l"(d) : "l"(a), "l"(b), "l"(c)); return d;
}
__device__ __forceinline__ u64 fadd2(u64 a, u64 b) {
    u64 d; asm("add.rn.f32x2 %0, %1, %2;" : "=l"(d) : "l"(a), "l"(b)); return d;
}

// ---------------- Stage 1: 4 pixels per thread, vectorized ----------------
// Block bx covers p rows 4bx..4bx+3, all 256 q. Thread: (prow, 4 q pixels).
// The 4 q pixels share one yt cell; Ht read as float4.
__global__ void __launch_bounds__(256) stage1_kernel(
    const float* __restrict__ yt, const float* __restrict__ Ht)
{
    int tid  = threadIdx.x;
    int bx   = blockIdx.x;            // 0..63
    int t64  = tid & 63;              // q cell
    int prow = tid >> 6;              // 0..3
    int p    = (bx << 2) + prow;
    int idx  = (p << 8) + (t64 << 2); // float4-aligned pixel index
    int yoff = (bx << 6) + t64;       // (p/4)*64 + q/4  (p/4 == bx)

    int bbase = blockIdx.y << 3;      // 8 batches per block
    float4 acc[8];
#pragma unroll
    for (int bo = 0; bo < 8; bo++) acc[bo] = make_float4(0.f, 0.f, 0.f, 0.f);

    const float* ytbase = yt + ((long)bbase << 17) + yoff;
#pragma unroll
    for (int t = 0; t < T_; t++) {
        float4 h4 = *(const float4*)(Ht + (t << 16) + idx);
        const float* ytp = ytbase + (t << 12);
#pragma unroll
        for (int bo = 0; bo < 8; bo++) {
            float yv = ytp[(long)bo << 17];
            acc[bo].x = fmaf(h4.x, yv, acc[bo].x);
            acc[bo].y = fmaf(h4.y, yv, acc[bo].y);
            acc[bo].z = fmaf(h4.z, yv, acc[bo].z);
            acc[bo].w = fmaf(h4.w, yv, acc[bo].w);
        }
    }
#pragma unroll
    for (int bo = 0; bo < 8; bo++)
        *(float4*)(g_x + ((long)(bbase + bo) << 16) + idx) = acc[bo];
}

// ---------------- Stage 2: fused conv1+relu+conv2 ----------------
#define SHW 36
#define SH_ELEMS (8 * 34 * SHW)     // 39168 B
#define SX_ELEMS (36 * 40)          //  5760 B

__global__ void __launch_bounds__(256, 3) fused_conv_kernel(
    const float* __restrict__ W1, const float* __restrict__ b1,
    const float* __restrict__ W2, const float* __restrict__ b2,
    float* __restrict__ out)
{
    __shared__ __align__(16) float sh[SH_ELEMS];
    __shared__ __align__(16) float sx[SX_ELEMS];
    __shared__ float sw1[288];
    __shared__ float sb1[32];
    __shared__ u64  sw2p[288];        // paired (w,w) conv2 weights

    int tid = threadIdx.x;
    int b   = blockIdx.y;
    int P0  = (blockIdx.x >> 3) << 5;
    int Q0  = (blockIdx.x & 7)  << 5;
    const float* xb = g_x + ((long)b << 16);

    // ---- stage weights + x tile ----
    for (int i = tid; i < 288; i += 256) {
        sw1[i] = W1[i];
        float f = W2[i];
        sw2p[i] = pk2(f, f);
    }
    if (tid < 32) sb1[tid] = b1[tid];
    for (int i = tid; i < SX_ELEMS; i += 256) {
        int r  = i / 40;
        int cc = i - r * 40;
        int gp = P0 - 2 + r;
        int gq = Q0 - 2 + cc;
        float v = 0.f;
        if (cc < 36 && (unsigned)gp < 256u && (unsigned)gq < 256u)
            v = xb[(gp << 8) + gq];
        sx[i] = v;
    }
    __syncthreads();

    // conv1 mapping: 4 channel-pair slots x 64 spatial threads
    int pr = tid >> 6;
    int u0 = tid & 63;

    // conv2 mapping: 128 strips (2 rows x 4 cols) x 2 channel-halves
    int st   = tid & 127;
    int half = tid >> 7;
    int oy = (st >> 3) << 1;
    int ox = (st & 7) << 2;
    float bb = *b2;
    u64 A01, A23, B01, B23;           // packed accumulators (out0,out1),(out2,out3)
    A01 = A23 = B01 = B23 = (half == 0) ? pk2(bb, bb) : 0ull;

    for (int g = 0; g < 4; g++) {
        // ============ conv1 + relu: 2 channels per thread, x reused (scalar) ============
        {
            int c0 = (g << 3) + (pr << 1);
            float w0[9], w1[9];
#pragma unroll
            for (int k = 0; k < 9; k++) { w0[k] = sw1[c0 * 9 + k]; w1[k] = sw1[c0 * 9 + 9 + k]; }
            float bi0 = sb1[c0], bi1 = sb1[c0 + 1];
            float* sh0 = sh + (pr << 1) * (34 * SHW);
            float* sh1 = sh0 + 34 * SHW;

#pragma unroll
            for (int k = 0; k < 5; k++) {
                int unit = u0 + (k << 6);
                if (unit < 306) {
                    int r   = unit / 9;
                    int col = (unit - r * 9) << 2;
                    const float* x0 = sx + r * 40 + col;
                    float v[3][6];
#pragma unroll
                    for (int dy = 0; dy < 3; dy++) {
                        float4 q4 = *(const float4*)(x0 + dy * 40);
                        float2 q2 = *(const float2*)(x0 + dy * 40 + 4);
                        v[dy][0] = q4.x; v[dy][1] = q4.y; v[dy][2] = q4.z;
                        v[dy][3] = q4.w; v[dy][4] = q2.x; v[dy][5] = q2.y;
                    }
                    float a0 = bi0, a1 = bi0, a2 = bi0, a3 = bi0;
                    float c0a = bi1, c1a = bi1, c2a = bi1, c3a = bi1;
#pragma unroll
                    for (int dy = 0; dy < 3; dy++) {
#pragma unroll
                        for (int dx = 0; dx < 3; dx++) {
                            float wa = w0[dy * 3 + dx], wb = w1[dy * 3 + dx];
                            a0  = fmaf(wa, v[dy][dx + 0], a0);
                            a1  = fmaf(wa, v[dy][dx + 1], a1);
                            a2  = fmaf(wa, v[dy][dx + 2], a2);
                            a3  = fmaf(wa, v[dy][dx + 3], a3);
                            c0a = fmaf(wb, v[dy][dx + 0], c0a);
                            c1a = fmaf(wb, v[dy][dx + 1], c1a);
                            c2a = fmaf(wb, v[dy][dx + 2], c2a);
                            c3a = fmaf(wb, v[dy][dx + 3], c3a);
                        }
                    }
                    float mr  = ((unsigned)(P0 - 1 + r) < 256u) ? 1.f : 0.f;
                    int   gq  = Q0 - 1 + col;
                    float m0 = mr * (((unsigned)(gq + 0) < 256u) ? 1.f : 0.f);
                    float m1 = mr * (((unsigned)(gq + 1) < 256u) ? 1.f : 0.f);
                    float m2 = mr * (((unsigned)(gq + 2) < 256u) ? 1.f : 0.f);
                    float m3 = mr * (((unsigned)(gq + 3) < 256u) ? 1.f : 0.f);
                    *(float4*)(sh0 + r * SHW + col) = make_float4(
                        fmaxf(a0, 0.f) * m0, fmaxf(a1, 0.f) * m1,
                        fmaxf(a2, 0.f) * m2, fmaxf(a3, 0.f) * m3);
                    *(float4*)(sh1 + r * SHW + col) = make_float4(
                        fmaxf(c0a, 0.f) * m0, fmaxf(c1a, 0.f) * m1,
                        fmaxf(c2a, 0.f) * m2, fmaxf(c3a, 0.f) * m3);
                }
            }
        }
        __syncthreads();

        // ============ conv2: 2x4 outputs, 4 channels per half, packed f32x2 ============
        {
#pragma unroll
            for (int cc = 0; cc < 4; cc++) {
                int c8v = (half << 2) + cc;
                int c   = (g << 3) + c8v;
                u64 w9[9];
#pragma unroll
                for (int k = 0; k < 9; k++) w9[k] = sw2p[c * 9 + k];
                const float* hp = sh + c8v * (34 * SHW) + oy * SHW + ox;

#pragma unroll
                for (int j = 0; j < 4; j++) {
                    const float* rp = hp + j * SHW;        // 16B-aligned
                    ulonglong2 q = *(const ulonglong2*)rp; // (v0,v1),(v2,v3)
                    u64 p45 = *(const u64*)(rp + 4);       // (v4,v5)
                    u64 p01 = q.x, p23 = q.y;
                    float2 fa = upk2(p01), fb = upk2(p23), fc = upk2(p45);
                    u64 p12 = pk2(fa.y, fb.x);
                    u64 p34 = pk2(fb.y, fc.x);
                    if (j < 3) {                           // out row 0, dy=j
                        A01 = ffma2(w9[3 * j + 0], p01, A01);
                        A23 = ffma2(w9[3 * j + 0], p23, A23);
                        A01 = ffma2(w9[3 * j + 1], p12, A01);
                        A23 = ffma2(w9[3 * j + 1], p34, A23);
                        A01 = ffma2(w9[3 * j + 2], p23, A01);
                        A23 = ffma2(w9[3 * j + 2], p45, A23);
                    }
                    if (j >= 1) {                          // out row 1, dy=j-1
                        B01 = ffma2(w9[3 * (j - 1) + 0], p01, B01);
                        B23 = ffma2(w9[3 * (j - 1) + 0], p23, B23);
                        B01 = ffma2(w9[3 * (j - 1) + 1], p12, B01);
                        B23 = ffma2(w9[3 * (j - 1) + 1], p34, B23);
                        B01 = ffma2(w9[3 * (j - 1) + 2], p23, B01);
                        B23 = ffma2(w9[3 * (j - 1) + 2], p45, B23);
                    }
                }
            }
        }
        __syncthreads();   // before next group's conv1 overwrites sh
    }

    // ---- combine channel-halves via smem (sx no longer needed) ----
    u64* red = (u64*)sx;
    if (half == 1) {
        u64* rp = red + st * 4;
        rp[0] = A01; rp[1] = A23; rp[2] = B01; rp[3] = B23;
    }
    __syncthreads();
    if (half == 0) {
        const u64* rp = red + st * 4;
        A01 = fadd2(A01, rp[0]);
        A23 = fadd2(A23, rp[1]);
        B01 = fadd2(B01, rp[2]);
        B23 = fadd2(B23, rp[3]);
        float2 a = upk2(A01), c = upk2(A23), d = upk2(B01), e = upk2(B23);
        float* ob = out + ((long)b << 16) + ((P0 + oy) << 8) + Q0 + ox;
        *(float4*)ob         = make_float4(a.x, a.y, c.x, c.y);
        *(float4*)(ob + 256) = make_float4(d.x, d.y, e.x, e.y);
    }
}

// -------------------------------------------------------------------------
extern "C" void kernel_launch(void* const* d_in, const int* in_sizes, int n_in,
                              void* d_out, int out_size)
{
    const float* yt = (const float*)d_in[0];
    const float* Ht = (const float*)d_in[1];
    const float* W1 = (const float*)d_in[2];
    const float* b1 = (const float*)d_in[3];
    const float* W2 = (const float*)d_in[4];
    const float* b2 = (const float*)d_in[5];
    float* out = (float*)d_out;

    stage1_kernel<<<dim3(64, 4), 256>>>(yt, Ht);
    fused_conv_kernel<<<dim3(64, 32), 256>>>(W1, b1, W2, b2, out);
}

// round 10
// speedup vs baseline: 2.1830x; 1.1466x over previous
#include <cuda_runtime.h>

// -------------------------------------------------------------------------
// out = Conv2(ReLU(Conv1( sum_t Ht[t,:,:] * upsample4(yt[b,t]) )))
//   yt:(32,32,64,64) Ht:(32,256,256) W1:(32,1,3,3) b1:(32) W2:(1,32,3,3) b2:(1)
//   out:(32,1,256,256) f32
// -------------------------------------------------------------------------

#define B_ 32
#define T_ 32
#define R_ 256

__device__ float g_x[B_ * R_ * R_];   // stage-1 scratch (8.4 MB static)

// ---------------- Stage 1: 4 pixels per thread, vectorized ----------------
__global__ void __launch_bounds__(256) stage1_kernel(
    const float* __restrict__ yt, const float* __restrict__ Ht)
{
    int tid  = threadIdx.x;
    int bx   = blockIdx.x;            // 0..63
    int t64  = tid & 63;              // q cell
    int prow = tid >> 6;              // 0..3
    int p    = (bx << 2) + prow;
    int idx  = (p << 8) + (t64 << 2);
    int yoff = (bx << 6) + t64;

    int bbase = blockIdx.y << 3;      // 8 batches per block
    float4 acc[8];
#pragma unroll
    for (int bo = 0; bo < 8; bo++) acc[bo] = make_float4(0.f, 0.f, 0.f, 0.f);

    const float* ytbase = yt + ((long)bbase << 17) + yoff;
#pragma unroll
    for (int t = 0; t < T_; t++) {
        float4 h4 = *(const float4*)(Ht + (t << 16) + idx);
        const float* ytp = ytbase + (t << 12);
#pragma unroll
        for (int bo = 0; bo < 8; bo++) {
            float yv = ytp[(long)bo << 17];
            acc[bo].x = fmaf(h4.x, yv, acc[bo].x);
            acc[bo].y = fmaf(h4.y, yv, acc[bo].y);
            acc[bo].z = fmaf(h4.z, yv, acc[bo].z);
            acc[bo].w = fmaf(h4.w, yv, acc[bo].w);
        }
    }
#pragma unroll
    for (int bo = 0; bo < 8; bo++)
        *(float4*)(g_x + ((long)(bbase + bo) << 16) + idx) = acc[bo];
}

// ---------------- Stage 2: fused conv1+relu+conv2 ----------------
#define SHW 36
#define SH_ELEMS (8 * 34 * SHW)     // 39168 B
#define SX_ELEMS (36 * 40)          //  5760 B

__global__ void __launch_bounds__(256, 3) fused_conv_kernel(
    const float* __restrict__ W1, const float* __restrict__ b1,
    const float* __restrict__ W2, const float* __restrict__ b2,
    float* __restrict__ out)
{
    __shared__ __align__(16) float sh[SH_ELEMS];
    __shared__ __align__(16) float sx[SX_ELEMS];
    __shared__ float sw1[288];
    __shared__ float sb1[32];
    __shared__ float sw2[288];

    int tid = threadIdx.x;
    int b   = blockIdx.y;
    int P0  = (blockIdx.x >> 3) << 5;
    int Q0  = (blockIdx.x & 7)  << 5;
    const float* xb = g_x + ((long)b << 16);

    // ---- stage weights + x tile ----
    for (int i = tid; i < 288; i += 256) { sw1[i] = W1[i]; sw2[i] = W2[i]; }
    if (tid < 32) sb1[tid] = b1[tid];
    for (int i = tid; i < SX_ELEMS; i += 256) {
        int r  = i / 40;
        int cc = i - r * 40;
        int gp = P0 - 2 + r;
        int gq = Q0 - 2 + cc;
        float v = 0.f;
        if (cc < 36 && (unsigned)gp < 256u && (unsigned)gq < 256u)
            v = xb[(gp << 8) + gq];
        sx[i] = v;
    }
    __syncthreads();

    // conv1 mapping: (channel-pair, band, strip) = 4 x 7 x 9 = 252 threads
    int p4   = tid / 63;                 // 0..3 pair slot; 4 => inactive
    int rem  = tid - p4 * 63;
    int d    = rem / 9;                  // row band 0..6 (5 rows each)
    int s    = rem - d * 9;              // col strip 0..8
    int col  = s << 2;
    int r0   = d * 5;
    bool act = (p4 < 4);
    // column masks: h1 outside image -> 0 (conv2 SAME zero padding)
    float cm0 = ((unsigned)(Q0 - 1 + col + 0) < 256u) ? 1.f : 0.f;
    float cm1 = ((unsigned)(Q0 - 1 + col + 1) < 256u) ? 1.f : 0.f;
    float cm2 = ((unsigned)(Q0 - 1 + col + 2) < 256u) ? 1.f : 0.f;
    float cm3 = ((unsigned)(Q0 - 1 + col + 3) < 256u) ? 1.f : 0.f;

    // conv2 mapping: 128 strips (2 rows x 4 cols) x 2 channel-halves
    int st   = tid & 127;
    int half = tid >> 7;
    int oy = (st >> 3) << 1;
    int ox = (st & 7) << 2;
    float bb = *b2;
    float aA0, aA1, aA2, aA3, aB0, aB1, aB2, aB3;
    aA0 = aA1 = aA2 = aA3 = aB0 = aB1 = aB2 = aB3 = (half == 0) ? bb : 0.f;

    for (int g = 0; g < 4; g++) {
        // ===== conv1 + relu: marching rows, 2 channels per thread =====
        if (act) {
            int c0 = (g << 3) + (p4 << 1);
            float w0[9], w1[9];
#pragma unroll
            for (int k = 0; k < 9; k++) { w0[k] = sw1[c0 * 9 + k]; w1[k] = sw1[c0 * 9 + 9 + k]; }
            float bi0 = sb1[c0], bi1 = sb1[c0 + 1];
            float* sh0 = sh + (p4 << 1) * (34 * SHW);
            float* sh1 = sh0 + 34 * SHW;
            const float* xp = sx + r0 * 40 + col;

            float v[3][6];
#pragma unroll
            for (int j = 0; j < 2; j++) {
                float4 q4 = *(const float4*)(xp + j * 40);
                float2 q2 = *(const float2*)(xp + j * 40 + 4);
                v[j][0] = q4.x; v[j][1] = q4.y; v[j][2] = q4.z;
                v[j][3] = q4.w; v[j][4] = q2.x; v[j][5] = q2.y;
            }
#pragma unroll
            for (int i = 0; i < 5; i++) {
                int row = r0 + i;
                if (row < 34) {
                    float* vn = v[(i + 2) % 3];
                    {
                        float4 q4 = *(const float4*)(xp + (i + 2) * 40);
                        float2 q2 = *(const float2*)(xp + (i + 2) * 40 + 4);
                        vn[0] = q4.x; vn[1] = q4.y; vn[2] = q4.z;
                        vn[3] = q4.w; vn[4] = q2.x; vn[5] = q2.y;
                    }
                    const float* vr0 = v[i % 3];
                    const float* vr1 = v[(i + 1) % 3];
                    const float* vr2 = v[(i + 2) % 3];
                    float a0 = bi0, a1 = bi0, a2 = bi0, a3 = bi0;
                    float c0a = bi1, c1a = bi1, c2a = bi1, c3a = bi1;
#pragma unroll
                    for (int dx = 0; dx < 3; dx++) {
                        float wa0 = w0[dx], wa1 = w0[3 + dx], wa2 = w0[6 + dx];
                        float wb0 = w1[dx], wb1 = w1[3 + dx], wb2 = w1[6 + dx];
                        float x0 = vr0[dx + 0], x1 = vr0[dx + 1], x2 = vr0[dx + 2], x3 = vr0[dx + 3];
                        a0  = fmaf(wa0, x0, a0);  a1  = fmaf(wa0, x1, a1);
                        a2  = fmaf(wa0, x2, a2);  a3  = fmaf(wa0, x3, a3);
                        c0a = fmaf(wb0, x0, c0a); c1a = fmaf(wb0, x1, c1a);
                        c2a = fmaf(wb0, x2, c2a); c3a = fmaf(wb0, x3, c3a);
                        x0 = vr1[dx + 0]; x1 = vr1[dx + 1]; x2 = vr1[dx + 2]; x3 = vr1[dx + 3];
                        a0  = fmaf(wa1, x0, a0);  a1  = fmaf(wa1, x1, a1);
                        a2  = fmaf(wa1, x2, a2);  a3  = fmaf(wa1, x3, a3);
                        c0a = fmaf(wb1, x0, c0a); c1a = fmaf(wb1, x1, c1a);
                        c2a = fmaf(wb1, x2, c2a); c3a = fmaf(wb1, x3, c3a);
                        x0 = vr2[dx + 0]; x1 = vr2[dx + 1]; x2 = vr2[dx + 2]; x3 = vr2[dx + 3];
                        a0  = fmaf(wa2, x0, a0);  a1  = fmaf(wa2, x1, a1);
                        a2  = fmaf(wa2, x2, a2);  a3  = fmaf(wa2, x3, a3);
                        c0a = fmaf(wb2, x0, c0a); c1a = fmaf(wb2, x1, c1a);
                        c2a = fmaf(wb2, x2, c2a); c3a = fmaf(wb2, x3, c3a);
                    }
                    float mr = ((unsigned)(P0 - 1 + row) < 256u) ? 1.f : 0.f;
                    float m0 = mr * cm0, m1 = mr * cm1, m2 = mr * cm2, m3 = mr * cm3;
                    *(float4*)(sh0 + row * SHW + col) = make_float4(
                        fmaxf(a0, 0.f) * m0, fmaxf(a1, 0.f) * m1,
                        fmaxf(a2, 0.f) * m2, fmaxf(a3, 0.f) * m3);
                    *(float4*)(sh1 + row * SHW + col) = make_float4(
                        fmaxf(c0a, 0.f) * m0, fmaxf(c1a, 0.f) * m1,
                        fmaxf(c2a, 0.f) * m2, fmaxf(c3a, 0.f) * m3);
                }
            }
        }
        __syncthreads();

        // ===== conv2: 2x4 outputs, 4 channels per half (scalar) =====
        {
#pragma unroll
            for (int cc = 0; cc < 4; cc++) {
                int c8v = (half << 2) + cc;
                int c   = (g << 3) + c8v;
                float w[9];
#pragma unroll
                for (int k = 0; k < 9; k++) w[k] = sw2[c * 9 + k];
                const float* hp = sh + c8v * (34 * SHW) + oy * SHW + ox;

#pragma unroll
                for (int j = 0; j < 4; j++) {
                    float4 q4 = *(const float4*)(hp + j * SHW);
                    float2 q2 = *(const float2*)(hp + j * SHW + 4);
                    float v0 = q4.x, v1 = q4.y, v2 = q4.z,
                          v3 = q4.w, v4 = q2.x, v5 = q2.y;
                    if (j < 3) {                          // out row 0, dy=j
                        float w0 = w[3 * j], w1 = w[3 * j + 1], w2 = w[3 * j + 2];
                        aA0 = fmaf(w0, v0, aA0); aA0 = fmaf(w1, v1, aA0); aA0 = fmaf(w2, v2, aA0);
                        aA1 = fmaf(w0, v1, aA1); aA1 = fmaf(w1, v2, aA1); aA1 = fmaf(w2, v3, aA1);
                        aA2 = fmaf(w0, v2, aA2); aA2 = fmaf(w1, v3, aA2); aA2 = fmaf(w2, v4, aA2);
                        aA3 = fmaf(w0, v3, aA3); aA3 = fmaf(w1, v4, aA3); aA3 = fmaf(w2, v5, aA3);
                    }
                    if (j >= 1) {                         // out row 1, dy=j-1
                        float w0 = w[3 * (j - 1)], w1 = w[3 * (j - 1) + 1], w2 = w[3 * (j - 1) + 2];
                        aB0 = fmaf(w0, v0, aB0); aB0 = fmaf(w1, v1, aB0); aB0 = fmaf(w2, v2, aB0);
                        aB1 = fmaf(w0, v1, aB1); aB1 = fmaf(w1, v2, aB1); aB1 = fmaf(w2, v3, aB1);
                        aB2 = fmaf(w0, v2, aB2); aB2 = fmaf(w1, v3, aB2); aB2 = fmaf(w2, v4, aB2);
                        aB3 = fmaf(w0, v3, aB3); aB3 = fmaf(w1, v4, aB3); aB3 = fmaf(w2, v5, aB3);
                    }
                }
            }
        }
        __syncthreads();   // before next group's conv1 overwrites sh
    }

    // ---- combine channel-halves via smem (sx no longer needed) ----
    float* red = sx;
    if (half == 1) {
        float* rp = red + st * 8;
        rp[0] = aA0; rp[1] = aA1; rp[2] = aA2; rp[3] = aA3;
        rp[4] = aB0; rp[5] = aB1; rp[6] = aB2; rp[7] = aB3;
    }
    __syncthreads();
    if (half == 0) {
        const float* rp = red + st * 8;
        aA0 += rp[0]; aA1 += rp[1]; aA2 += rp[2]; aA3 += rp[3];
        aB0 += rp[4]; aB1 += rp[5]; aB2 += rp[6]; aB3 += rp[7];
        float* ob = out + ((long)b << 16) + ((P0 + oy) << 8) + Q0 + ox;
        *(float4*)ob         = make_float4(aA0, aA1, aA2, aA3);
        *(float4*)(ob + 256) = make_float4(aB0, aB1, aB2, aB3);
    }
}

// -------------------------------------------------------------------------
extern "C" void kernel_launch(void* const* d_in, const int* in_sizes, int n_in,
                              void* d_out, int out_size)
{
    const float* yt = (const float*)d_in[0];
    const float* Ht = (const float*)d_in[1];
    const float* W1 = (const float*)d_in[2];
    const float* b1 = (const float*)d_in[3];
    const float* W2 = (const float*)d_in[4];
    const float* b2 = (const float*)d_in[5];
    float* out = (float*)d_out;

    stage1_kernel<<<dim3(64, 4), 256>>>(yt, Ht);
    fused_conv_kernel<<<dim3(64, 32), 256>>>(W1, b1, W2, b2, out);
}